// round 17
// baseline (speedup 1.0000x reference)
#include <cuda_runtime.h>

// ---------------------------------------------------------------------------
// Problem constants
// ---------------------------------------------------------------------------
#define BATCH   4
#define NPOS    196608          // 256*256*3 positions per batch
#define F       64              // filters
#define NCHUNK  512             // chunks per batch (scan granularity)
#define CS      384             // positions per chunk (multiple of 3)
#define TP      48              // positions staged in smem per tile (16 pixels)
#define NT      (CS / TP)       // 8 tiles per chunk
#define FT      24              // final-kernel tile positions
#define SCALE   (1.0f/196608.0f)

typedef unsigned long long ull;

// ---------------------------------------------------------------------------
// Scratch (device globals: allocation-free per harness rules)
// ---------------------------------------------------------------------------
__device__ float g_bufA[(size_t)BATCH * NPOS * F];   // 201 MB
__device__ float g_bufB[(size_t)BATCH * NPOS * F];   // 201 MB
__device__ float g_csum[BATCH * NCHUNK * F];
__device__ float g_off [BATCH * NCHUNK * F];

// ---------------------------------------------------------------------------
// Packed f32x2 helpers (sm_103a packed FMA pipe)
// ---------------------------------------------------------------------------
__device__ __forceinline__ ull pack2(float a, float b) {
    ull r; asm("mov.b64 %0, {%1,%2};" : "=l"(r) : "f"(a), "f"(b)); return r;
}
__device__ __forceinline__ void unpack2(ull v, float& a, float& b) {
    asm("mov.b64 {%0,%1}, %2;" : "=f"(a), "=f"(b) : "l"(v));
}
__device__ __forceinline__ ull ffma2(ull a, ull b, ull c) {
    ull d; asm("fma.rn.f32x2 %0, %1, %2, %3;" : "=l"(d) : "l"(a), "l"(b), "l"(c));
    return d;
}
__device__ __forceinline__ ull fadd2(ull a, ull b) {
    ull d; asm("add.rn.f32x2 %0, %1, %2;" : "=l"(d) : "l"(a), "l"(b));
    return d;
}

// cp.async helpers (fire-and-forget gmem->smem, no register scoreboard)
__device__ __forceinline__ void cpasync16(void* dst_smem, const void* src) {
    unsigned d = (unsigned)__cvta_generic_to_shared(dst_smem);
    asm volatile("cp.async.cg.shared.global [%0], [%1], 16;" :: "r"(d), "l"(src));
}
__device__ __forceinline__ void cpasync_commit() {
    asm volatile("cp.async.commit_group;" ::: "memory");
}
__device__ __forceinline__ void cpasync_wait0() {
    asm volatile("cp.async.wait_group 0;" ::: "memory");
}
__device__ __forceinline__ void cpasync_wait1() {
    asm volatile("cp.async.wait_group 1;" ::: "memory");
}

// ---------------------------------------------------------------------------
// Layer 0: x -> ReLU(w0[c]*x + b0[c]) -> chunk-local cumsum into g_bufA
// One block per (batch, chunk); 64 threads, thread = feature e.
// ---------------------------------------------------------------------------
__global__ __launch_bounds__(64)
void layer0_kernel(const int* __restrict__ ex,
                   const float* __restrict__ W0,   // [3][1][64]
                   const float* __restrict__ b0) { // [3][64]
    int batch = blockIdx.x / NCHUNK;
    int chunk = blockIdx.x % NCHUNK;
    int e = threadIdx.x;
    size_t base = (size_t)batch * NPOS + (size_t)chunk * CS;

    float w[3], bb[3];
#pragma unroll
    for (int c = 0; c < 3; ++c) { w[c] = W0[c * 64 + e]; bb[c] = b0[c * 64 + e]; }

    __shared__ int xs[96];
    float run = 0.0f;
    float* out = g_bufA + base * F;
    const int* exb = ex + base;

    for (int tile = 0; tile < CS / 96; ++tile) {
        __syncthreads();
        xs[threadIdx.x] = exb[tile * 96 + threadIdx.x];
        if (threadIdx.x < 32) xs[threadIdx.x + 64] = exb[tile * 96 + threadIdx.x + 64];
        __syncthreads();
#pragma unroll
        for (int px = 0; px < 32; ++px) {
#pragma unroll
            for (int c = 0; c < 3; ++c) {
                int p = px * 3 + c;
                float xf = (float)xs[p] * 0.25f - 1.0f;   // /8*2-1
                float v = fmaxf(fmaf(w[c], xf, bb[c]), 0.0f);
                run += v;
                out[(size_t)(tile * 96 + p) * F + e] = run;
            }
        }
    }
    g_csum[(batch * NCHUNK + chunk) * F + e] = run;
}

// ---------------------------------------------------------------------------
// Parallel exclusive scan over chunk sums -> per-chunk offsets.
// grid = (BATCH, F), block = 512 threads (one per chunk).
// ---------------------------------------------------------------------------
__global__ __launch_bounds__(512)
void scan_kernel() {
    int b = blockIdx.x;
    int e = blockIdx.y;
    int t = threadIdx.x;            // chunk index 0..511
    int lane = t & 31, w = t >> 5;  // 16 warps

    int i = (b * NCHUNK + t) * F + e;
    float v = g_csum[i];

    float s = v;
#pragma unroll
    for (int d = 1; d < 32; d <<= 1) {
        float n = __shfl_up_sync(0xffffffffu, s, d);
        if (lane >= d) s += n;
    }

    __shared__ float ws[16];
    if (lane == 31) ws[w] = s;
    __syncthreads();
    if (t < 16) {
        float x = ws[t];
#pragma unroll
        for (int d = 1; d < 16; d <<= 1) {
            float n = __shfl_up_sync(0x0000ffffu, x, d);
            if (t >= d) x += n;
        }
        ws[t] = x;
    }
    __syncthreads();

    float warp_pre = (w > 0) ? ws[w - 1] : 0.0f;
    g_off[i] = warp_pre + (s - v);   // exclusive prefix
}

// ---------------------------------------------------------------------------
// No-op parity kernel (launch-index shift for ncu capture targeting).
// ---------------------------------------------------------------------------
__global__ void parity_kernel() {}

// ---------------------------------------------------------------------------
// Mid layers 1..3.  Offset fold:  W^T((in+off)*SCALE) = (W*SCALE)^T in +
// (W^T off)*SCALE.  Triple-buffered cp.async staging, prefetch distance 2.
// __launch_bounds__(128,4): 4 resident blocks/SM (4 warps/SMSP) pins the
// FMA pipe at its floor; ptxas gets a 128-reg budget (weights=96 + misc).
// `rev` flips the block->chunk map so this layer reads the PREVIOUS layer's
// buffer in reverse write order -> tail of prior writes hits in L2.
// 128 threads: thread = (feature e, d-half h).
// ---------------------------------------------------------------------------
__global__ __launch_bounds__(128, 4)
void layer_kernel(int src, int rev,
                  const float* __restrict__ W,      // [3][64][64] (c,d,e)
                  const float* __restrict__ bias) { // [3][64]
    int batch = blockIdx.x / NCHUNK;
    int chunk = blockIdx.x % NCHUNK;
    if (rev) chunk = NCHUNK - 1 - chunk;
    int tid = threadIdx.x;
    int lane = tid & 31, wrp = tid >> 5;
    int e = wrp * 16 + (lane >> 1);
    int h = lane & 1;

    const float* in = src ? g_bufB : g_bufA;
    float*       out = src ? g_bufA : g_bufB;
    size_t base = (size_t)batch * NPOS + (size_t)chunk * CS;
    in  += base * F;
    out += base * F;

    const float* offv = g_off + (batch * NCHUNK + chunk) * F;

    // Register-resident weight columns, pre-scaled by SCALE.
    // offdot folded into bias (partner half combined by the same shfl as tot).
    ull wr[3][8][2];
    float od[3];
#pragma unroll
    for (int c = 0; c < 3; ++c) {
        float acc = 0.0f;
#pragma unroll
        for (int j = 0; j < 8; ++j) {
            int d0 = 8 * j + 4 * h;
            float w0 = W[(c * 64 + d0    ) * 64 + e];
            float w1 = W[(c * 64 + d0 + 1) * 64 + e];
            float w2 = W[(c * 64 + d0 + 2) * 64 + e];
            float w3 = W[(c * 64 + d0 + 3) * 64 + e];
            acc += w0 * offv[d0] + w1 * offv[d0 + 1]
                 + w2 * offv[d0 + 2] + w3 * offv[d0 + 3];
            wr[c][j][0] = pack2(w0 * SCALE, w1 * SCALE);
            wr[c][j][1] = pack2(w2 * SCALE, w3 * SCALE);
        }
        od[c] = acc * SCALE + bias[c * 64 + e];  // folded into bias
    }

    __shared__ float us[3][TP * F];   // triple buffer, 36 KB
    float run = 0.0f;

    // Preload tiles 0 and 1 (two committed groups), wait for tile 0 only.
#pragma unroll
    for (int pt = 0; pt < 2; ++pt) {
        const float4* in4 = reinterpret_cast<const float4*>(in + (size_t)pt * TP * F);
        float4* s4 = reinterpret_cast<float4*>(us[pt]);
#pragma unroll
        for (int k = 0; k < TP * F / 512; ++k)     // 6 float4 / thread
            cpasync16(&s4[tid + k * 128], &in4[tid + k * 128]);
        cpasync_commit();
    }
    cpasync_wait1();
    __syncthreads();

    for (int tile = 0; tile < NT; ++tile) {
        int cur = tile % 3;
        // Fire-and-forget prefetch of tile+2 into the retired buffer.
        if (tile + 2 < NT) {
            const float4* in4 = reinterpret_cast<const float4*>(
                in + (size_t)(tile + 2) * TP * F);
            float4* s4 = reinterpret_cast<float4*>(us[(tile + 2) % 3]);
#pragma unroll
            for (int k = 0; k < TP * F / 512; ++k)
                cpasync16(&s4[tid + k * 128], &in4[tid + k * 128]);
            cpasync_commit();
        }

#pragma unroll 2
        for (int px = 0; px < TP / 3; ++px) {
#pragma unroll
            for (int c = 0; c < 3; ++c) {
                int p = px * 3 + c;
                ull accA = 0ull, accB = 0ull;
#pragma unroll
                for (int j = 0; j < 8; ++j) {
                    ulonglong2 uv = *reinterpret_cast<const ulonglong2*>(
                        &us[cur][p * F + 8 * j + 4 * h]);
                    accA = ffma2(wr[c][j][0], uv.x, accA);
                    accB = ffma2(wr[c][j][1], uv.y, accB);
                }
                float a0, a1;
                unpack2(fadd2(accA, accB), a0, a1);
                float part = a0 + a1 + od[c];          // od includes bias
                float tot = part + __shfl_xor_sync(0xffffffffu, part, 1);
                run += fmaxf(tot, 0.0f);
                if (h == 0) out[(size_t)(tile * TP + p) * F + e] = run;
            }
        }

        // Group committed at tile-1 (for tile+1) is already long done:
        // wait retires instantly.  Tail tiles use wait0 for the last group.
        if (tile + 2 < NT) cpasync_wait1(); else cpasync_wait0();
        __syncthreads();
    }
    if (h == 0) g_csum[(batch * NCHUNK + chunk) * F + e] = run;
}

// ---------------------------------------------------------------------------
// Final dense 64 -> 8 logits, offset folded into bias; cp.async double
// buffer, one barrier per tile.  192 threads = 24 pos x 8 logits.
// Reads bufB forward (L3 wrote reversed -> low chunks written last -> hit L2).
// ---------------------------------------------------------------------------
__global__ __launch_bounds__(192)
void final_kernel(const float* __restrict__ Wf,   // [3][64][8]
                  const float* __restrict__ bf,   // [3][8]
                  float* __restrict__ outp) {
    int batch = blockIdx.x / NCHUNK;
    int chunk = blockIdx.x % NCHUNK;
    int tid = threadIdx.x;
    int ps = tid >> 3;           // 0..23 (position in tile; channel = ps % 3)
    int k  = tid & 7;            // output logit
    int c  = ps % 3;

    size_t base = (size_t)batch * NPOS + (size_t)chunk * CS;
    const float* in = g_bufB + base * F;
    const float* offv = g_off + (batch * NCHUNK + chunk) * F;

    float wreg[64];
    float bv = bf[c * 8 + k];
#pragma unroll
    for (int e = 0; e < 64; ++e) {
        float w = Wf[(c * 64 + e) * 8 + k];
        bv += w * offv[e] * SCALE;       // fold offset into bias
        wreg[e] = w * SCALE;             // pre-scale weight
    }

    __shared__ float us[2][FT * 68];   // pad 68; quads stay 16B aligned

    // Preload tile 0: FT*F/4 = 384 quads, threads 0..191 copy 2 each.
    {
#pragma unroll
        for (int q = 0; q < 2; ++q) {
            int idx = tid + q * 192;          // quad index
            int p = idx >> 4, qd = idx & 15;  // position, quad-within-row
            cpasync16(&us[0][p * 68 + qd * 4], in + p * 64 + qd * 4);
        }
        cpasync_commit();
        cpasync_wait0();
    }
    __syncthreads();

    for (int tile = 0; tile < CS / FT; ++tile) {
        int cur = tile & 1;
        if (tile + 1 < CS / FT) {
            const float* inT = in + (size_t)(tile + 1) * FT * F;
#pragma unroll
            for (int q = 0; q < 2; ++q) {
                int idx = tid + q * 192;
                int p = idx >> 4, qd = idx & 15;
                cpasync16(&us[cur ^ 1][p * 68 + qd * 4], inT + p * 64 + qd * 4);
            }
            cpasync_commit();
        }

        float acc = bv;
#pragma unroll
        for (int j = 0; j < 16; ++j) {
            float4 u4 = *reinterpret_cast<const float4*>(&us[cur][ps * 68 + 4 * j]);
            acc = fmaf(u4.x, wreg[4 * j    ], acc);
            acc = fmaf(u4.y, wreg[4 * j + 1], acc);
            acc = fmaf(u4.z, wreg[4 * j + 2], acc);
            acc = fmaf(u4.w, wreg[4 * j + 3], acc);
        }
        outp[(base + (size_t)(tile * FT + ps)) * 8 + k] = acc;

        cpasync_wait0();
        __syncthreads();
    }
}

// ---------------------------------------------------------------------------
// Launch: L0 -> scan -> L1(rev) -> scan -> parity -> L2(fwd) -> scan ->
// L3(rev) -> scan -> final(fwd).  Alternating chunk order gives each
// consumer L2 hits on the tail of its producer's writes.
// Graph-capturable: launches only.  Ping-pong: L1 A->B, L2 B->A, L3 A->B.
// ---------------------------------------------------------------------------
extern "C" void kernel_launch(void* const* d_in, const int* in_sizes, int n_in,
                              void* d_out, int out_size) {
    const int*   ex = (const int*)  d_in[0];
    const float* W0 = (const float*)d_in[1];
    const float* b0 = (const float*)d_in[2];
    const float* Wr = (const float*)d_in[3];   // [3][3][64][64]
    const float* br = (const float*)d_in[4];   // [3][3][64]
    const float* Wf = (const float*)d_in[5];   // [3][64][8]
    const float* bf = (const float*)d_in[6];   // [3][8]
    float* outp = (float*)d_out;

    dim3 grid(BATCH * NCHUNK);
    dim3 sgrid(BATCH, F);

    layer0_kernel<<<grid, 64>>>(ex, W0, b0);                      // 1
    scan_kernel<<<sgrid, 512>>>();                                // 2

    layer_kernel<<<grid, 128>>>(0, 1, Wr + 0 * 3 * 64 * 64, br + 0 * 3 * 64); // 3
    scan_kernel<<<sgrid, 512>>>();                                // 4

    parity_kernel<<<1, 32>>>();                                   // 5

    layer_kernel<<<grid, 128>>>(1, 0, Wr + 1 * 3 * 64 * 64, br + 1 * 3 * 64); // 6 <- ncu
    scan_kernel<<<sgrid, 512>>>();                                // 7

    layer_kernel<<<grid, 128>>>(0, 1, Wr + 2 * 3 * 64 * 64, br + 2 * 3 * 64); // 8
    scan_kernel<<<sgrid, 512>>>();                                // 9

    final_kernel<<<grid, 192>>>(Wf, bf, outp);                    // 10
}